// round 10
// baseline (speedup 1.0000x reference)
#include <cuda_runtime.h>
#include <math.h>

// Problem constants
#define N_CAPS 64
#define CAPS_DIM 16
#define OUT_DIM 128
#define P_DIM 1152
#define BATCH 256
#define BO (BATCH * OUT_DIM)       // 32768
#define PSPLIT 24
#define PCHUNK (P_DIM / PSPLIT)    // 48
#define WROW 132                   // padded row stride (float4-aligned, conflict-free)

// Scratch (no cudaMalloc allowed)
__device__ __align__(16) float g_partial[PSPLIT * BO];     // 3 MB
__device__ __align__(16) float g_wsum[N_CAPS * OUT_DIM];   // [n][o], 32 KB

// ---------------------------------------------------------------------------
// Kernel 1 (fused): grid (32, PSPLIT+1) x 256.
//  y < PSPLIT : X partials. x is (P, B, O) => matrix (P, 32768 floats).
//  y == PSPLIT: Wsum[n,o] = sum_c w[n,c,o] (float4), hidden inside the
//               HBM-bound reduction.
// ---------------------------------------------------------------------------
__global__ void __launch_bounds__(256) reduce_x_kernel(const float4* __restrict__ x4,
                                                       const float4* __restrict__ w4) {
    int chunk = blockIdx.y;

    if (chunk == PSPLIT) {
        int i = blockIdx.x * blockDim.x + threadIdx.x;   // float4 index into Wsum
        if (i >= N_CAPS * (OUT_DIM / 4)) return;
        int n  = i >> 5;                                 // 32 float4 per row
        int o4 = i & 31;
        const float4* base = w4 + (size_t)n * (CAPS_DIM * OUT_DIM / 4) + o4;
        float4 acc = make_float4(0.f, 0.f, 0.f, 0.f);
#pragma unroll
        for (int c = 0; c < CAPS_DIM; ++c) {
            float4 v = __ldg(&base[c * (OUT_DIM / 4)]);
            acc.x += v.x; acc.y += v.y; acc.z += v.z; acc.w += v.w;
        }
        reinterpret_cast<float4*>(g_wsum)[i] = acc;
        return;
    }

    int col = blockIdx.x * blockDim.x + threadIdx.x;     // 0..8191 (float4 units)
    const float4* base = x4 + (size_t)(chunk * PCHUNK) * (BO / 4) + col;

    float4 acc = make_float4(0.f, 0.f, 0.f, 0.f);
#pragma unroll 8
    for (int p = 0; p < PCHUNK; ++p) {
        float4 v = __ldcs(&base[(size_t)p * (BO / 4)]);
        acc.x += v.x; acc.y += v.y; acc.z += v.z; acc.w += v.w;
    }
    reinterpret_cast<float4*>(g_partial)[chunk * (BO / 4) + col] = acc;
}

// ---------------------------------------------------------------------------
// Kernel 2: routing, warp-per-batch. 32 blocks x 256 threads; warp wid owns
// batch b = 8*bid + wid; lane l owns o-quad [4l, 4l+4). After one
// __syncthreads (W staging) everything is in-warp: no block barriers.
// ---------------------------------------------------------------------------
__global__ void __launch_bounds__(256) routing_kernel(float* __restrict__ out) {
    const int t   = threadIdx.x;
    const int wid = t >> 5;
    const int l   = t & 31;
    const int b   = blockIdx.x * 8 + wid;
    const int o0  = l * 4;

    __shared__ __align__(16) float sh_w[N_CAPS * WROW];   // padded Wsum rows
    __shared__ __align__(16) float shrp[8][OUT_DIM];      // per-warp rp
    __shared__ float shc[8][N_CAPS];                       // per-warp coeffs

    // ---- Phase A: batched W loads (8 float4/thread, MLP=8) ----
    float4 wv[8];
    {
        const float4* w4 = reinterpret_cast<const float4*>(g_wsum);
#pragma unroll
        for (int k = 0; k < 8; ++k)
            wv[k] = __ldg(&w4[t + k * 256]);
    }

    // X quad for this lane (24 independent coalesced LDG.128)
    float4 X = make_float4(0.f, 0.f, 0.f, 0.f);
#pragma unroll
    for (int ch = 0; ch < PSPLIT; ++ch) {
        float4 v = *reinterpret_cast<const float4*>(&g_partial[ch * BO + b * OUT_DIM + o0]);
        X.x += v.x; X.y += v.y; X.z += v.z; X.w += v.w;
    }

    // ---- Phase B: store W to padded shared ----
#pragma unroll
    for (int k = 0; k < 8; ++k) {
        int i4 = t + k * 256;
        int n  = i4 >> 5;
        int o  = (i4 & 31) * 4;
        *reinterpret_cast<float4*>(&sh_w[n * WROW + o]) = wv[k];
    }

    shc[wid][l]      = 1.0f / N_CAPS;
    shc[wid][l + 32] = 1.0f / N_CAPS;
    float logit_a = 0.f, logit_b = 0.f;     // caps l and l+32
    __syncthreads();                         // the ONLY block barrier

    float4 s = make_float4(0.f, 0.f, 0.f, 0.f);
    float scale = 0.f;

    // ITERATIONS = 3 -> 2 routing updates, then final squash
    for (int iter = 0; iter < 3; ++iter) {
        // s quad: s_o = X_o * sum_n c_n W[n,o]   (row-quad LDS.128 + bcast c)
        s = make_float4(0.f, 0.f, 0.f, 0.f);
        const float* c = shc[wid];
#pragma unroll
        for (int n = 0; n < N_CAPS; ++n) {
            float cn = c[n];
            float4 wq = *reinterpret_cast<const float4*>(&sh_w[n * WROW + o0]);
            s.x += cn * wq.x; s.y += cn * wq.y; s.z += cn * wq.z; s.w += cn * wq.w;
        }
        s.x *= X.x; s.y *= X.y; s.z *= X.z; s.w *= X.w;

        // ||s||^2 via in-warp reduce
        float sq = s.x * s.x + s.y * s.y + s.z * s.z + s.w * s.w;
#pragma unroll
        for (int off = 16; off > 0; off >>= 1)
            sq += __shfl_xor_sync(0xffffffffu, sq, off);
        scale = sqrtf(sq) / (1.0f + sq);     // norm / (1 + norm^2)

        if (iter == 2) break;

        // rp quad to per-warp shared
        float4 rp = make_float4(scale * s.x * X.x, scale * s.y * X.y,
                                scale * s.z * X.z, scale * s.w * X.w);
        *reinterpret_cast<float4*>(&shrp[wid][o0]) = rp;
        __syncwarp();

        // logits for caps l and l+32: 32 float4 along o, rp shared by both
        {
            const float4* row_a = reinterpret_cast<const float4*>(&sh_w[l * WROW]);
            const float4* row_b = reinterpret_cast<const float4*>(&sh_w[(l + 32) * WROW]);
            const float4* rp4   = reinterpret_cast<const float4*>(&shrp[wid][0]);
            float aa = 0.f, bb = 0.f;
#pragma unroll
            for (int j = 0; j < OUT_DIM / 4; ++j) {
                float4 r  = rp4[j];
                float4 wa = row_a[j];
                float4 wb = row_b[j];
                aa += wa.x * r.x + wa.y * r.y + wa.z * r.z + wa.w * r.w;
                bb += wb.x * r.x + wb.y * r.y + wb.z * r.z + wb.w * r.w;
            }
            logit_a += aa;
            logit_b += bb;
        }

        // softmax over 64 logits, fully in-warp
        float m = fmaxf(logit_a, logit_b);
#pragma unroll
        for (int off = 16; off > 0; off >>= 1)
            m = fmaxf(m, __shfl_xor_sync(0xffffffffu, m, off));
        float ea = __expf(logit_a - m);
        float eb = __expf(logit_b - m);
        float sm = ea + eb;
#pragma unroll
        for (int off = 16; off > 0; off >>= 1)
            sm += __shfl_xor_sync(0xffffffffu, sm, off);
        float inv = 1.0f / sm;
        shc[wid][l]      = ea * inv;
        shc[wid][l + 32] = eb * inv;
        __syncwarp();
    }

    // final squash(coeffs @ xp)
    float4 o = make_float4(scale * s.x, scale * s.y, scale * s.z, scale * s.w);
    *reinterpret_cast<float4*>(&out[b * OUT_DIM + o0]) = o;
}

// ---------------------------------------------------------------------------
extern "C" void kernel_launch(void* const* d_in, const int* in_sizes, int n_in,
                              void* d_out, int out_size) {
    const float* x = (const float*)d_in[0];             // (1152, 256, 128)
    const float* w = (const float*)d_in[1];             // (64, 16, 128)
    float* out = (float*)d_out;                         // (256, 1, 128)

    dim3 g1(32, PSPLIT + 1);
    reduce_x_kernel<<<g1, 256>>>(reinterpret_cast<const float4*>(x),
                                 reinterpret_cast<const float4*>(w));
    routing_kernel<<<BATCH / 8, 256>>>(out);
}

// round 11
// speedup vs baseline: 1.1657x; 1.1657x over previous
#include <cuda_runtime.h>
#include <math.h>

// Problem constants
#define N_CAPS 64
#define CAPS_DIM 16
#define OUT_DIM 128
#define P_DIM 1152
#define BATCH 256
#define BO (BATCH * OUT_DIM)       // 32768
#define BO4 (BO / 4)               // 8192 float4 per p-row
#define WROW 132                   // padded row stride (float4-aligned, conflict-free)

#define THREADS 512
#define NB_W 4                     // wsum blocks (bids 0..3)
#define NB_X 256                   // one block per batch element
#define NBLK (NB_W + NB_X)         // 260 — all co-resident (no 2nd wave)

// Scratch (no cudaMalloc allowed)
__device__ __align__(16) float g_wsum[N_CAPS * OUT_DIM];   // 32 KB
__device__ int g_wflag;   // wsum blocks done (target NB_W)
__device__ int g_xdone;   // x blocks done (target NB_X) -> resets counters

// ---------------------------------------------------------------------------
// Single fused kernel.
//  bids 0..3   : Wsum[n,o] = sum_c w[n,c,o]  (2048 float4 outputs, 1/thread)
//  bids 4..259 : batch b = bid-4. Stream x[:, b, :] from DRAM (148 MB total
//                across blocks, read once), reduce over p in registers, then
//                run the full routing epilogue in-block.
// All 260 blocks are co-resident => the wflag wait can never deadlock and in
// practice never spins (wsum finishes ~2us in, x streaming takes ~20us).
// ---------------------------------------------------------------------------
__global__ void __launch_bounds__(THREADS, 2) capsule_fused(
    const float4* __restrict__ x4,        // (1152, 256, 128) fp32
    const float4* __restrict__ w4,        // (64, 16, 128) fp32
    float* __restrict__ out)              // (256, 1, 128)
{
    const int bid = blockIdx.x;
    const int t   = threadIdx.x;

    // ---------------- wsum blocks ----------------
    if (bid < NB_W) {
        int i4 = bid * THREADS + t;                      // 0..2047
        int n  = i4 >> 5;
        int o4 = i4 & 31;
        const float4* base = w4 + (size_t)n * (CAPS_DIM * OUT_DIM / 4) + o4;
        float4 acc = make_float4(0.f, 0.f, 0.f, 0.f);
#pragma unroll
        for (int c = 0; c < CAPS_DIM; ++c) {
            float4 v = __ldg(&base[c * (OUT_DIM / 4)]);
            acc.x += v.x; acc.y += v.y; acc.z += v.z; acc.w += v.w;
        }
        reinterpret_cast<float4*>(g_wsum)[i4] = acc;
        __threadfence();
        __syncthreads();
        if (t == 0) atomicAdd(&g_wflag, 1);
        return;
    }

    // ---------------- x blocks: stream + reduce + route ----------------
    const int b  = bid - NB_W;
    const int g  = t >> 5;        // p-row group 0..15
    const int o4 = t & 31;        // float4 column within the batch slice
    const int lane = t & 31;
    const int wid  = t >> 5;

    __shared__ __align__(16) float sh_red[16][OUT_DIM];    // 8 KB group partials
    __shared__ __align__(16) float sh_w[N_CAPS * WROW];    // 33.8 KB padded Wsum
    __shared__ __align__(16) float shrp[OUT_DIM];
    __shared__ float shpart[128];
    __shared__ float shc[N_CAPS];
    __shared__ float shred[4];

    // Stream x[:, b, :]: warp g reads p = g, g+16, g+32, ... (512B/row/warp)
    {
        const float4* base = x4 + (size_t)g * BO4 + b * 32 + o4;
        float4 acc = make_float4(0.f, 0.f, 0.f, 0.f);
#pragma unroll 8
        for (int i = 0; i < P_DIM / 16; ++i) {            // 72 iterations
            float4 v = __ldcs(&base[(size_t)i * 16 * BO4]);
            acc.x += v.x; acc.y += v.y; acc.z += v.z; acc.w += v.w;
        }
        *reinterpret_cast<float4*>(&sh_red[g][o4 * 4]) = acc;
    }

    // Wait for wsum (long done by now), then stage W to padded shared
    if (t == 0) {
        volatile int* f = &g_wflag;
        while (*f < NB_W) __nanosleep(32);
    }
    __syncthreads();          // also publishes sh_red
    __threadfence();
    {
        float4 wv[4];
        const float4* gw4 = reinterpret_cast<const float4*>(g_wsum);
#pragma unroll
        for (int k = 0; k < 4; ++k)
            wv[k] = __ldg(&gw4[t + k * THREADS]);
#pragma unroll
        for (int k = 0; k < 4; ++k) {
            int i4 = t + k * THREADS;
            int n  = i4 >> 5;
            int o  = (i4 & 31) * 4;
            *reinterpret_cast<float4*>(&sh_w[n * WROW + o]) = wv[k];
        }
    }

    // Finalize X[o] for routing threads (t<128): sum the 16 group partials
    float X = 0.f;
    if (t < 128) {
#pragma unroll
        for (int gg = 0; gg < 16; ++gg)
            X += sh_red[gg][t];
    }

    if (t < N_CAPS) shc[t] = 1.0f / N_CAPS;
    float logit_a = 0.f, logit_b = 0.f;   // warp 0: caps lane, lane+32
    __syncthreads();

    // ---------------- routing: ITERATIONS=3 -> 2 updates + final squash ----
    for (int iter = 0; iter < 3; ++iter) {
        float s = 0.f;
        if (t < 128) {
            // s_o = X * sum_n c_n W[n,o]  (column LDS, lanes consecutive)
#pragma unroll
            for (int n = 0; n < N_CAPS; ++n)
                s += shc[n] * sh_w[n * WROW + t];
            s *= X;

            float sq = s * s;
#pragma unroll
            for (int off = 16; off > 0; off >>= 1)
                sq += __shfl_xor_sync(0xffffffffu, sq, off);
            if (lane == 0) shred[wid] = sq;
        }
        __syncthreads();
        float tot   = shred[0] + shred[1] + shred[2] + shred[3];
        float scale = sqrtf(tot) / (1.0f + tot);   // norm / (1 + norm^2)

        if (iter == 2) {
            if (t < 128) out[b * OUT_DIM + t] = scale * s;
            break;
        }

        if (t < 128) shrp[t] = scale * s * X;
        __syncthreads();

        if (t < 128) {
            // logits partial: cap (t&63), o-half (t>>6), float4 LDS rows
            int n_id = t & 63, oh = t >> 6;
            const float4* wrow = reinterpret_cast<const float4*>(&sh_w[n_id * WROW]) + oh * 16;
            const float4* rp4  = reinterpret_cast<const float4*>(shrp) + oh * 16;
            float acc = 0.f;
#pragma unroll
            for (int j = 0; j < 16; ++j) {
                float4 w4v = wrow[j];
                float4 r4v = rp4[j];
                acc += w4v.x * r4v.x + w4v.y * r4v.y + w4v.z * r4v.z + w4v.w * r4v.w;
            }
            shpart[t] = acc;
        }
        __syncthreads();

        if (t < 32) {
            logit_a += shpart[t]      + shpart[t + 64];
            logit_b += shpart[t + 32] + shpart[t + 96];
            float m = fmaxf(logit_a, logit_b);
#pragma unroll
            for (int off = 16; off > 0; off >>= 1)
                m = fmaxf(m, __shfl_xor_sync(0xffffffffu, m, off));
            float ea = __expf(logit_a - m);
            float eb = __expf(logit_b - m);
            float sm = ea + eb;
#pragma unroll
            for (int off = 16; off > 0; off >>= 1)
                sm += __shfl_xor_sync(0xffffffffu, sm, off);
            float inv = 1.0f / sm;
            shc[t]      = ea * inv;
            shc[t + 32] = eb * inv;
        }
        __syncthreads();
    }

    // Completion count + counter reset (graph-replay safe; every block reads
    // g_wflag before incrementing g_xdone, so reset can't race a reader)
    if (t == 0) {
        __threadfence();
        int v = atomicAdd(&g_xdone, 1);
        if (v == NB_X - 1) {
            g_wflag = 0;
            g_xdone = 0;
            __threadfence();
        }
    }
}

// ---------------------------------------------------------------------------
extern "C" void kernel_launch(void* const* d_in, const int* in_sizes, int n_in,
                              void* d_out, int out_size) {
    const float* x = (const float*)d_in[0];             // (1152, 256, 128)
    const float* w = (const float*)d_in[1];             // (64, 16, 128)
    float* out = (float*)d_out;                         // (256, 1, 128)

    capsule_fused<<<NBLK, THREADS>>>(reinterpret_cast<const float4*>(x),
                                     reinterpret_cast<const float4*>(w),
                                     out);
}

// round 12
// speedup vs baseline: 1.2051x; 1.0338x over previous
#include <cuda_runtime.h>
#include <math.h>

// Problem constants
#define N_CAPS 64
#define CAPS_DIM 16
#define OUT_DIM 128
#define P_DIM 1152
#define BATCH 256
#define BO (BATCH * OUT_DIM)       // 32768
#define BO4 (BO / 4)               // 8192 float4 per p-row
#define WROW 132                   // padded row stride (float4-aligned, conflict-free)

#define THREADS 512
#define NB_W 4                     // wsum blocks (bids 0..3)
#define NB_X 256                   // one block per batch element
#define NBLK (NB_W + NB_X)         // 260 — all co-resident (no 2nd wave)

// Scratch (no cudaMalloc allowed)
__device__ __align__(16) float g_wsum[N_CAPS * OUT_DIM];   // 32 KB
__device__ int g_wflag;   // wsum blocks done (target NB_W)
__device__ int g_xdone;   // x blocks done (target NB_X) -> resets counters

// ---------------------------------------------------------------------------
// Single fused kernel.
//  bids 0..3   : Wsum[n,o] = sum_c w[n,c,o]
//  bids 4..259 : batch b = bid-4: stream x[:, b, :] once from DRAM, reduce
//                over p, then routing epilogue in-block (warps 4..15 exit
//                after staging; epilogue runs on 4 warps, 3 barriers/iter).
// ---------------------------------------------------------------------------
__global__ void __launch_bounds__(THREADS, 2) capsule_fused(
    const float4* __restrict__ x4,        // (1152, 256, 128) fp32
    const float4* __restrict__ w4,        // (64, 16, 128) fp32
    float* __restrict__ out)              // (256, 1, 128)
{
    const int bid = blockIdx.x;
    const int t   = threadIdx.x;

    // ---------------- wsum blocks ----------------
    if (bid < NB_W) {
        int i4 = bid * THREADS + t;                      // 0..2047
        int n  = i4 >> 5;
        int o4 = i4 & 31;
        const float4* base = w4 + (size_t)n * (CAPS_DIM * OUT_DIM / 4) + o4;
        float4 acc = make_float4(0.f, 0.f, 0.f, 0.f);
#pragma unroll
        for (int c = 0; c < CAPS_DIM; ++c) {
            float4 v = __ldg(&base[c * (OUT_DIM / 4)]);
            acc.x += v.x; acc.y += v.y; acc.z += v.z; acc.w += v.w;
        }
        reinterpret_cast<float4*>(g_wsum)[i4] = acc;
        __threadfence();
        __syncthreads();
        if (t == 0) atomicAdd(&g_wflag, 1);
        return;
    }

    // ---------------- x blocks: stream + reduce + route ----------------
    const int b    = bid - NB_W;
    const int g    = t >> 5;      // p-row group 0..15
    const int o4   = t & 31;      // float4 column within the batch slice
    const int lane = t & 31;
    const int wid  = t >> 5;

    __shared__ __align__(16) float sh_red[16][OUT_DIM];    // 8 KB group partials
    __shared__ __align__(16) float sh_w[N_CAPS * WROW];    // 33.8 KB padded Wsum
    __shared__ __align__(16) float shrp0[OUT_DIM];         // pre-scale routed vec
    __shared__ float shpart[128];
    __shared__ float shc[N_CAPS];
    __shared__ float shred[4];

    // Stream x[:, b, :]: warp g reads p = g, g+16, g+32, ... (512B/row/warp)
    {
        const float4* base = x4 + (size_t)g * BO4 + b * 32 + o4;
        float4 acc = make_float4(0.f, 0.f, 0.f, 0.f);
#pragma unroll 8
        for (int i = 0; i < P_DIM / 16; ++i) {            // 72 iterations
            float4 v = __ldcs(&base[(size_t)i * 16 * BO4]);
            acc.x += v.x; acc.y += v.y; acc.z += v.z; acc.w += v.w;
        }
        *reinterpret_cast<float4*>(&sh_red[g][o4 * 4]) = acc;
    }

    // Wait for wsum (long done by now)
    if (t == 0) {
        volatile int* f = &g_wflag;
        while (*f < NB_W) __nanosleep(32);
    }
    __syncthreads();          // publishes sh_red + orders after spin
    __threadfence();

    // Stage W to padded shared (all 512 threads, batched loads)
    {
        float4 wv[4];
        const float4* gw4 = reinterpret_cast<const float4*>(g_wsum);
#pragma unroll
        for (int k = 0; k < 4; ++k)
            wv[k] = __ldg(&gw4[t + k * THREADS]);
#pragma unroll
        for (int k = 0; k < 4; ++k) {
            int i4 = t + k * THREADS;
            int n  = i4 >> 5;
            int o  = (i4 & 31) * 4;
            *reinterpret_cast<float4*>(&sh_w[n * WROW + o]) = wv[k];
        }
    }
    if (t < N_CAPS) shc[t] = 1.0f / N_CAPS;
    __syncthreads();          // sh_w + shc visible

    // Completion/reset bookkeeping is done by an exiting warp's thread after
    // it has no more shared work; it must run in every block exactly once.
    if (t == 256) {
        __threadfence();
        int v = atomicAdd(&g_xdone, 1);
        if (v == NB_X - 1) {
            g_wflag = 0;
            g_xdone = 0;
            __threadfence();
        }
    }
    if (wid >= 4) return;     // 12 warps exit; epilogue barriers = 4 warps

    // Finalize X[o]: sum the 16 group partials
    float X = 0.f;
#pragma unroll
    for (int gg = 0; gg < 16; ++gg)
        X += sh_red[gg][t];

    float logit_a = 0.f, logit_b = 0.f;   // warp 0: caps lane, lane+32

    // ---------------- routing: 2 updates + final squash, 3 BAR/iter --------
    for (int iter = 0; iter < 3; ++iter) {
        // s_o = X * sum_n c_n W[n,o]  (column LDS, lanes consecutive)
        float s = 0.f;
#pragma unroll
        for (int n = 0; n < N_CAPS; ++n)
            s += shc[n] * sh_w[n * WROW + t];
        s *= X;

        // publish pre-scale rp AND norm partial before ONE sync
        float sq = s * s;
#pragma unroll
        for (int off = 16; off > 0; off >>= 1)
            sq += __shfl_xor_sync(0xffffffffu, sq, off);
        if (lane == 0) shred[wid] = sq;
        shrp0[t] = s * X;                      // pre-scale routed vector
        __syncthreads();

        float tot   = shred[0] + shred[1] + shred[2] + shred[3];
        float scale = sqrtf(tot) / (1.0f + tot);   // norm / (1 + norm^2)

        if (iter == 2) {
            out[b * OUT_DIM + t] = scale * s;      // final squash
            break;
        }

        // logits partial: cap (t&63), o-half (t>>6); scale folded in here
        {
            int n_id = t & 63, oh = t >> 6;
            const float4* wrow = reinterpret_cast<const float4*>(&sh_w[n_id * WROW]) + oh * 16;
            const float4* rp4  = reinterpret_cast<const float4*>(shrp0) + oh * 16;
            float acc = 0.f;
#pragma unroll
            for (int j = 0; j < 16; ++j) {
                float4 w4v = wrow[j];
                float4 r4v = rp4[j];
                acc += w4v.x * r4v.x + w4v.y * r4v.y + w4v.z * r4v.z + w4v.w * r4v.w;
            }
            shpart[t] = scale * acc;
        }
        __syncthreads();

        // warp 0: accumulate logits (2 caps/lane) + softmax fully in-warp
        if (t < 32) {
            logit_a += shpart[t]      + shpart[t + 64];
            logit_b += shpart[t + 32] + shpart[t + 96];
            float m = fmaxf(logit_a, logit_b);
#pragma unroll
            for (int off = 16; off > 0; off >>= 1)
                m = fmaxf(m, __shfl_xor_sync(0xffffffffu, m, off));
            float ea = __expf(logit_a - m);
            float eb = __expf(logit_b - m);
            float sm = ea + eb;
#pragma unroll
            for (int off = 16; off > 0; off >>= 1)
                sm += __shfl_xor_sync(0xffffffffu, sm, off);
            float inv = 1.0f / sm;
            shc[t]      = ea * inv;
            shc[t + 32] = eb * inv;
        }
        __syncthreads();
    }
}

// ---------------------------------------------------------------------------
extern "C" void kernel_launch(void* const* d_in, const int* in_sizes, int n_in,
                              void* d_out, int out_size) {
    const float* x = (const float*)d_in[0];             // (1152, 256, 128)
    const float* w = (const float*)d_in[1];             // (64, 16, 128)
    float* out = (float*)d_out;                         // (256, 1, 128)

    capsule_fused<<<NBLK, THREADS>>>(reinterpret_cast<const float4*>(x),
                                     reinterpret_cast<const float4*>(w),
                                     out);
}